// round 1
// baseline (speedup 1.0000x reference)
#include <cuda_runtime.h>
#include <cstdint>

#define D_MODEL_C 1024
#define DK_C 64
#define B_C 4
#define S_C 4096
#define NROWS_C (B_C * S_C)

// Scratch for projected Q, K, V (fp32). Static device arrays: allocation-free.
__device__ float g_Q[NROWS_C * DK_C];
__device__ float g_K[NROWS_C * DK_C];
__device__ float g_V[NROWS_C * DK_C];

static __device__ __forceinline__ uint32_t f2tf32(float f) {
    uint32_t u;
    asm("cvt.rna.tf32.f32 %0, %1;" : "=r"(u) : "f"(f));
    return u;
}
static __device__ __forceinline__ float exp2_approx(float x) {
    float y;
    asm("ex2.approx.f32 %0, %1;" : "=f"(y) : "f"(x));
    return y;
}
static __device__ __forceinline__ void mma_tf32(float c[4], const uint32_t a[4], const uint32_t b[2]) {
    asm volatile(
        "mma.sync.aligned.m16n8k8.row.col.f32.tf32.tf32.f32 "
        "{%0,%1,%2,%3}, {%4,%5,%6,%7}, {%8,%9}, {%0,%1,%2,%3};\n"
        : "+f"(c[0]), "+f"(c[1]), "+f"(c[2]), "+f"(c[3])
        : "r"(a[0]), "r"(a[1]), "r"(a[2]), "r"(a[3]), "r"(b[0]), "r"(b[1]));
}

// ---------------------------------------------------------------------------
// Kernel 1: fused QKV projection, 3xTF32 split precision (near-fp32 accuracy).
// Block: 64 rows x 64 cols x 3 matrices, 128 threads (4 warps, m16 slab each).
// ---------------------------------------------------------------------------
#define PKC 16          // K-chunk
#define ES_S 20         // emb smem stride: 20 mod 32 = 4*? -> banks 4r+c conflict-free
#define WS_S 72         // W smem stride: 72 mod 32 = 8 -> banks 8k+c conflict-free

__global__ __launch_bounds__(128)
void qkv_proj_kernel(const float* __restrict__ emb,
                     const float* __restrict__ Wq, const float* __restrict__ bq,
                     const float* __restrict__ Wk, const float* __restrict__ bk,
                     const float* __restrict__ Wv, const float* __restrict__ bv)
{
    __shared__ float Es[2][64 * ES_S];        // [hi|lo] emb tile 64x16
    __shared__ float Ws[2][3][PKC * WS_S];    // [hi|lo] W tiles 16x64 x3

    const int tid  = threadIdx.x;
    const int warp = tid >> 5;
    const int lane = tid & 31;
    const int row0 = blockIdx.x * 64;

    const float* Wm[3] = {Wq, Wk, Wv};

    float acc[3][8][4];
#pragma unroll
    for (int w = 0; w < 3; ++w)
#pragma unroll
        for (int n = 0; n < 8; ++n)
#pragma unroll
            for (int j = 0; j < 4; ++j) acc[w][n][j] = 0.f;

    const int ar = warp * 16 + (lane >> 2);   // A-fragment row (first of pair)
    const int ac = lane & 3;                  // A-fragment col within k8

    for (int kc = 0; kc < D_MODEL_C / PKC; ++kc) {
        __syncthreads();
        // Load emb tile 64x16 (256 float4), split hi/lo tf32
#pragma unroll
        for (int i = 0; i < 2; ++i) {
            int id = tid + i * 128;
            int r = id >> 2, c4 = (id & 3) * 4;
            float4 v = *reinterpret_cast<const float4*>(
                &emb[(size_t)(row0 + r) * D_MODEL_C + kc * PKC + c4]);
            float* dh = &Es[0][r * ES_S + c4];
            float* dl = &Es[1][r * ES_S + c4];
            float h;
            h = __uint_as_float(f2tf32(v.x)); dh[0] = h; dl[0] = __uint_as_float(f2tf32(v.x - h));
            h = __uint_as_float(f2tf32(v.y)); dh[1] = h; dl[1] = __uint_as_float(f2tf32(v.y - h));
            h = __uint_as_float(f2tf32(v.z)); dh[2] = h; dl[2] = __uint_as_float(f2tf32(v.z - h));
            h = __uint_as_float(f2tf32(v.w)); dh[3] = h; dl[3] = __uint_as_float(f2tf32(v.w - h));
        }
        // Load W tiles 3 x 16x64 (256 float4 each), split hi/lo tf32
#pragma unroll
        for (int w = 0; w < 3; ++w) {
#pragma unroll
            for (int i = 0; i < 2; ++i) {
                int id = tid + i * 128;
                int r = id >> 4, c4 = (id & 15) * 4;
                float4 v = *reinterpret_cast<const float4*>(
                    &Wm[w][(size_t)(kc * PKC + r) * DK_C + c4]);
                float* dh = &Ws[0][w][r * WS_S + c4];
                float* dl = &Ws[1][w][r * WS_S + c4];
                float h;
                h = __uint_as_float(f2tf32(v.x)); dh[0] = h; dl[0] = __uint_as_float(f2tf32(v.x - h));
                h = __uint_as_float(f2tf32(v.y)); dh[1] = h; dl[1] = __uint_as_float(f2tf32(v.y - h));
                h = __uint_as_float(f2tf32(v.z)); dh[2] = h; dl[2] = __uint_as_float(f2tf32(v.z - h));
                h = __uint_as_float(f2tf32(v.w)); dh[3] = h; dl[3] = __uint_as_float(f2tf32(v.w - h));
            }
        }
        __syncthreads();
#pragma unroll
        for (int ks = 0; ks < PKC / 8; ++ks) {
            uint32_t ah[4], al[4];
            ah[0] = __float_as_uint(Es[0][ar * ES_S + ks * 8 + ac]);
            ah[1] = __float_as_uint(Es[0][(ar + 8) * ES_S + ks * 8 + ac]);
            ah[2] = __float_as_uint(Es[0][ar * ES_S + ks * 8 + ac + 4]);
            ah[3] = __float_as_uint(Es[0][(ar + 8) * ES_S + ks * 8 + ac + 4]);
            al[0] = __float_as_uint(Es[1][ar * ES_S + ks * 8 + ac]);
            al[1] = __float_as_uint(Es[1][(ar + 8) * ES_S + ks * 8 + ac]);
            al[2] = __float_as_uint(Es[1][ar * ES_S + ks * 8 + ac + 4]);
            al[3] = __float_as_uint(Es[1][(ar + 8) * ES_S + ks * 8 + ac + 4]);
#pragma unroll
            for (int w = 0; w < 3; ++w) {
#pragma unroll
                for (int n = 0; n < 8; ++n) {
                    const int brow = ks * 8 + ac;
                    const int bcol = n * 8 + (lane >> 2);
                    uint32_t bh[2], bl[2];
                    bh[0] = __float_as_uint(Ws[0][w][brow * WS_S + bcol]);
                    bh[1] = __float_as_uint(Ws[0][w][(brow + 4) * WS_S + bcol]);
                    bl[0] = __float_as_uint(Ws[1][w][brow * WS_S + bcol]);
                    bl[1] = __float_as_uint(Ws[1][w][(brow + 4) * WS_S + bcol]);
                    // 3xTF32: hi*hi + hi*lo + lo*hi (lo*lo dropped)
                    mma_tf32(acc[w][n], ah, bh);
                    mma_tf32(acc[w][n], ah, bl);
                    mma_tf32(acc[w][n], al, bh);
                }
            }
        }
    }
    // Epilogue: bias add, write fp32 scratch (float2 stores, C-layout contiguous pairs)
    const float* bias[3] = {bq, bk, bv};
    float* outp[3] = {g_Q, g_K, g_V};
    const int r  = row0 + ar;
    const int cb = (lane & 3) * 2;
#pragma unroll
    for (int w = 0; w < 3; ++w) {
#pragma unroll
        for (int n = 0; n < 8; ++n) {
            int col = n * 8 + cb;
            float b0 = bias[w][col], b1 = bias[w][col + 1];
            *reinterpret_cast<float2*>(&outp[w][(size_t)r * DK_C + col]) =
                make_float2(acc[w][n][0] + b0, acc[w][n][1] + b1);
            *reinterpret_cast<float2*>(&outp[w][(size_t)(r + 8) * DK_C + col]) =
                make_float2(acc[w][n][2] + b0, acc[w][n][3] + b1);
        }
    }
}

// ---------------------------------------------------------------------------
// Kernel 2: flash attention (FA2-style), Br=Bc=64, 4 warps, single-pass tf32.
// Softmax in exp2 domain; P round-trips via smem (KP buffer reused K->P).
// ---------------------------------------------------------------------------
#define KV_S 72   // stride 72 mod 32 = 8 -> conflict-free fragment LDS

__global__ __launch_bounds__(128)
void attn_kernel(float* __restrict__ out)
{
    __shared__ float KP[64 * KV_S];   // Q staging, then K tile, then P tile
    __shared__ float Vs[64 * KV_S];   // V tile

    const int tid  = threadIdx.x;
    const int warp = tid >> 5;
    const int lane = tid & 31;
    const int b    = blockIdx.y;
    const int q0   = blockIdx.x * 64;

    const float* Qg = g_Q + ((size_t)b * S_C + q0) * DK_C;
    const float* Kg = g_K + (size_t)b * S_C * DK_C;
    const float* Vg = g_V + (size_t)b * S_C * DK_C;

    // Stage Q tile raw into KP (64 rows x 16 float4 = 1024 float4)
#pragma unroll
    for (int i = 0; i < 8; ++i) {
        int id = tid + i * 128;
        int r = id >> 4, c4 = (id & 15) * 4;
        *reinterpret_cast<float4*>(&KP[r * KV_S + c4]) =
            *reinterpret_cast<const float4*>(&Qg[(size_t)r * DK_C + c4]);
    }
    __syncthreads();

    const int ar = warp * 16 + (lane >> 2);
    const int ac = lane & 3;
    // Fold softmax scale (1/sqrt(64)) and log2(e) into Q before tf32 rounding
    const float qsc = 1.4426950408889634f * 0.125f;
    uint32_t qf[8][4];
#pragma unroll
    for (int ks = 0; ks < 8; ++ks) {
        qf[ks][0] = f2tf32(KP[ar * KV_S + ks * 8 + ac] * qsc);
        qf[ks][1] = f2tf32(KP[(ar + 8) * KV_S + ks * 8 + ac] * qsc);
        qf[ks][2] = f2tf32(KP[ar * KV_S + ks * 8 + ac + 4] * qsc);
        qf[ks][3] = f2tf32(KP[(ar + 8) * KV_S + ks * 8 + ac + 4] * qsc);
    }

    float o[8][4];
#pragma unroll
    for (int n = 0; n < 8; ++n)
#pragma unroll
        for (int j = 0; j < 4; ++j) o[n][j] = 0.f;
    float m0 = -1e30f, m1 = -1e30f, l0 = 0.f, l1 = 0.f;

    for (int t = 0; t < S_C / 64; ++t) {
        __syncthreads();   // all warps done with previous P (KP) and V reads
        const float* Kt = Kg + (size_t)t * 64 * DK_C;
        const float* Vt = Vg + (size_t)t * 64 * DK_C;
#pragma unroll
        for (int i = 0; i < 8; ++i) {
            int id = tid + i * 128;
            int r = id >> 4, c4 = (id & 15) * 4;
            float4 kv = *reinterpret_cast<const float4*>(&Kt[(size_t)r * DK_C + c4]);
            float4 vv = *reinterpret_cast<const float4*>(&Vt[(size_t)r * DK_C + c4]);
            float* kd = &KP[r * KV_S + c4];
            float* vd = &Vs[r * KV_S + c4];
            kd[0] = __uint_as_float(f2tf32(kv.x));
            kd[1] = __uint_as_float(f2tf32(kv.y));
            kd[2] = __uint_as_float(f2tf32(kv.z));
            kd[3] = __uint_as_float(f2tf32(kv.w));
            vd[0] = __uint_as_float(f2tf32(vv.x));
            vd[1] = __uint_as_float(f2tf32(vv.y));
            vd[2] = __uint_as_float(f2tf32(vv.z));
            vd[3] = __uint_as_float(f2tf32(vv.w));
        }
        __syncthreads();

        // S = (Q * qsc) @ K^T   (log2-domain logits)
        float s[8][4];
#pragma unroll
        for (int n = 0; n < 8; ++n)
#pragma unroll
            for (int j = 0; j < 4; ++j) s[n][j] = 0.f;
#pragma unroll
        for (int ks = 0; ks < 8; ++ks) {
#pragma unroll
            for (int n = 0; n < 8; ++n) {
                uint32_t bf[2];
                bf[0] = __float_as_uint(KP[(n * 8 + (lane >> 2)) * KV_S + ks * 8 + ac]);
                bf[1] = __float_as_uint(KP[(n * 8 + (lane >> 2)) * KV_S + ks * 8 + ac + 4]);
                mma_tf32(s[n], qf[ks], bf);
            }
        }

        // Online softmax (row pair r0 = ar, r1 = ar+8; quad reduce over lanes%4)
        float mx0 = m0, mx1 = m1;
#pragma unroll
        for (int n = 0; n < 8; ++n) {
            mx0 = fmaxf(mx0, fmaxf(s[n][0], s[n][1]));
            mx1 = fmaxf(mx1, fmaxf(s[n][2], s[n][3]));
        }
        mx0 = fmaxf(mx0, __shfl_xor_sync(0xffffffffu, mx0, 1));
        mx0 = fmaxf(mx0, __shfl_xor_sync(0xffffffffu, mx0, 2));
        mx1 = fmaxf(mx1, __shfl_xor_sync(0xffffffffu, mx1, 1));
        mx1 = fmaxf(mx1, __shfl_xor_sync(0xffffffffu, mx1, 2));
        float a0 = exp2_approx(m0 - mx0);
        float a1 = exp2_approx(m1 - mx1);
        float rs0 = 0.f, rs1 = 0.f;
#pragma unroll
        for (int n = 0; n < 8; ++n) {
            s[n][0] = exp2_approx(s[n][0] - mx0);
            s[n][1] = exp2_approx(s[n][1] - mx0);
            s[n][2] = exp2_approx(s[n][2] - mx1);
            s[n][3] = exp2_approx(s[n][3] - mx1);
            rs0 += s[n][0] + s[n][1];
            rs1 += s[n][2] + s[n][3];
        }
        rs0 += __shfl_xor_sync(0xffffffffu, rs0, 1);
        rs0 += __shfl_xor_sync(0xffffffffu, rs0, 2);
        rs1 += __shfl_xor_sync(0xffffffffu, rs1, 1);
        rs1 += __shfl_xor_sync(0xffffffffu, rs1, 2);
        l0 = l0 * a0 + rs0;
        l1 = l1 * a1 + rs1;
        m0 = mx0; m1 = mx1;
#pragma unroll
        for (int n = 0; n < 8; ++n) {
            o[n][0] *= a0; o[n][1] *= a0; o[n][2] *= a1; o[n][3] *= a1;
        }

        __syncthreads();   // all warps done reading K tile before overwriting with P
        {
            const int pc = (lane & 3) * 2;
#pragma unroll
            for (int n = 0; n < 8; ++n) {
                KP[ar * KV_S + n * 8 + pc]           = __uint_as_float(f2tf32(s[n][0]));
                KP[ar * KV_S + n * 8 + pc + 1]       = __uint_as_float(f2tf32(s[n][1]));
                KP[(ar + 8) * KV_S + n * 8 + pc]     = __uint_as_float(f2tf32(s[n][2]));
                KP[(ar + 8) * KV_S + n * 8 + pc + 1] = __uint_as_float(f2tf32(s[n][3]));
            }
        }
        __syncwarp();      // P region is warp-private (own 16 rows)

        // O += P @ V
#pragma unroll
        for (int ks = 0; ks < 8; ++ks) {
            uint32_t a[4];
            a[0] = __float_as_uint(KP[ar * KV_S + ks * 8 + ac]);
            a[1] = __float_as_uint(KP[(ar + 8) * KV_S + ks * 8 + ac]);
            a[2] = __float_as_uint(KP[ar * KV_S + ks * 8 + ac + 4]);
            a[3] = __float_as_uint(KP[(ar + 8) * KV_S + ks * 8 + ac + 4]);
#pragma unroll
            for (int n = 0; n < 8; ++n) {
                uint32_t bf[2];
                bf[0] = __float_as_uint(Vs[(ks * 8 + ac) * KV_S + n * 8 + (lane >> 2)]);
                bf[1] = __float_as_uint(Vs[(ks * 8 + ac + 4) * KV_S + n * 8 + (lane >> 2)]);
                mma_tf32(o[n], a, bf);
            }
        }
    }

    // Epilogue: normalize by l, write output
    const float i0 = 1.f / l0, i1 = 1.f / l1;
    float* ob = out + ((size_t)b * S_C + q0) * DK_C;
    const int cb = (lane & 3) * 2;
#pragma unroll
    for (int n = 0; n < 8; ++n) {
        int col = n * 8 + cb;
        *reinterpret_cast<float2*>(&ob[(size_t)(warp * 16 + (lane >> 2)) * DK_C + col]) =
            make_float2(o[n][0] * i0, o[n][1] * i0);
        *reinterpret_cast<float2*>(&ob[(size_t)(warp * 16 + (lane >> 2) + 8) * DK_C + col]) =
            make_float2(o[n][2] * i1, o[n][3] * i1);
    }
}

// ---------------------------------------------------------------------------
extern "C" void kernel_launch(void* const* d_in, const int* in_sizes, int n_in,
                              void* d_out, int out_size) {
    (void)in_sizes; (void)n_in; (void)out_size;
    const float* emb = (const float*)d_in[0];
    const float* Wq  = (const float*)d_in[1];
    const float* bq  = (const float*)d_in[2];
    const float* Wk  = (const float*)d_in[3];
    const float* bk  = (const float*)d_in[4];
    const float* Wv  = (const float*)d_in[5];
    const float* bv  = (const float*)d_in[6];

    qkv_proj_kernel<<<NROWS_C / 64, 128>>>(emb, Wq, bq, Wk, bk, Wv, bv);
    dim3 grid(S_C / 64, B_C);
    attn_kernel<<<grid, 128>>>((float*)d_out);
}

// round 3
// speedup vs baseline: 1.1454x; 1.1454x over previous
#include <cuda_runtime.h>
#include <cstdint>

#define D_MODEL_C 1024
#define DK_C 64
#define B_C 4
#define S_C 4096
#define NROWS_C (B_C * S_C)
#define NSPLIT 4
#define KV_PER_SPLIT (S_C / NSPLIT)      // 1024
#define TILES_PER_SPLIT (KV_PER_SPLIT / 64)  // 16

// Scratch (fp32). Static device arrays: allocation-free.
__device__ float g_Q[NROWS_C * DK_C];
__device__ float g_K[NROWS_C * DK_C];
__device__ float g_V[NROWS_C * DK_C];
__device__ float g_Opart[NSPLIT * NROWS_C * DK_C];   // unnormalized partial O
__device__ float g_m[NSPLIT * NROWS_C];
__device__ float g_l[NSPLIT * NROWS_C];

static __device__ __forceinline__ uint32_t f2tf32(float f) {
    uint32_t u;
    asm("cvt.rna.tf32.f32 %0, %1;" : "=r"(u) : "f"(f));
    return u;
}
static __device__ __forceinline__ float exp2_approx(float x) {
    float y;
    asm("ex2.approx.f32 %0, %1;" : "=f"(y) : "f"(x));
    return y;
}
static __device__ __forceinline__ void mma_tf32(float c[4], const uint32_t a[4], const uint32_t b[2]) {
    asm volatile(
        "mma.sync.aligned.m16n8k8.row.col.f32.tf32.tf32.f32 "
        "{%0,%1,%2,%3}, {%4,%5,%6,%7}, {%8,%9}, {%0,%1,%2,%3};\n"
        : "+f"(c[0]), "+f"(c[1]), "+f"(c[2]), "+f"(c[3])
        : "r"(a[0]), "r"(a[1]), "r"(a[2]), "r"(a[3]), "r"(b[0]), "r"(b[1]));
}

// ---------------------------------------------------------------------------
// Kernel 1: fused QKV projection, 3xTF32 split precision.
// 256 threads (8 warps): warp = (row-slab 0..3) x (col-half 0..1).
// Each warp: 16 rows x 32 cols x 3 matrices.
// ---------------------------------------------------------------------------
#define PKC 16          // K-chunk
#define ES_S 20         // 20 mod 32 = 20 -> a-frag banks 20g+ac all distinct
#define WS_S 72         // 72 mod 32 = 8  -> b-frag banks 8ac+g all distinct

__global__ __launch_bounds__(256)
void qkv_proj_kernel(const float* __restrict__ emb,
                     const float* __restrict__ Wq, const float* __restrict__ bq,
                     const float* __restrict__ Wk, const float* __restrict__ bk,
                     const float* __restrict__ Wv, const float* __restrict__ bv)
{
    __shared__ float Es[2][64 * ES_S];        // [hi|lo] emb tile 64x16
    __shared__ float Ws[2][3][PKC * WS_S];    // [hi|lo] W tiles 16x64 x3

    const int tid  = threadIdx.x;
    const int warp = tid >> 5;
    const int lane = tid & 31;
    const int rs   = warp & 3;      // row slab
    const int ch   = warp >> 2;     // col half
    const int row0 = blockIdx.x * 64;

    const float* Wm[3] = {Wq, Wk, Wv};

    float acc[3][4][4];
#pragma unroll
    for (int w = 0; w < 3; ++w)
#pragma unroll
        for (int n = 0; n < 4; ++n)
#pragma unroll
            for (int j = 0; j < 4; ++j) acc[w][n][j] = 0.f;

    const int ar = rs * 16 + (lane >> 2);
    const int ac = lane & 3;
    const int g  = lane >> 2;

    for (int kc = 0; kc < D_MODEL_C / PKC; ++kc) {
        __syncthreads();
        // emb tile 64x16 = 256 float4, one per thread
        {
            int r = tid >> 2, c4 = (tid & 3) * 4;
            float4 v = *reinterpret_cast<const float4*>(
                &emb[(size_t)(row0 + r) * D_MODEL_C + kc * PKC + c4]);
            float* dh = &Es[0][r * ES_S + c4];
            float* dl = &Es[1][r * ES_S + c4];
            float h;
            h = __uint_as_float(f2tf32(v.x)); dh[0] = h; dl[0] = __uint_as_float(f2tf32(v.x - h));
            h = __uint_as_float(f2tf32(v.y)); dh[1] = h; dl[1] = __uint_as_float(f2tf32(v.y - h));
            h = __uint_as_float(f2tf32(v.z)); dh[2] = h; dl[2] = __uint_as_float(f2tf32(v.z - h));
            h = __uint_as_float(f2tf32(v.w)); dh[3] = h; dl[3] = __uint_as_float(f2tf32(v.w - h));
        }
        // W tiles: 3 x (16x64) = 256 float4 each, one per thread per matrix
#pragma unroll
        for (int w = 0; w < 3; ++w) {
            int r = tid >> 4, c4 = (tid & 15) * 4;
            float4 v = *reinterpret_cast<const float4*>(
                &Wm[w][(size_t)(kc * PKC + r) * DK_C + c4]);
            float* dh = &Ws[0][w][r * WS_S + c4];
            float* dl = &Ws[1][w][r * WS_S + c4];
            float h;
            h = __uint_as_float(f2tf32(v.x)); dh[0] = h; dl[0] = __uint_as_float(f2tf32(v.x - h));
            h = __uint_as_float(f2tf32(v.y)); dh[1] = h; dl[1] = __uint_as_float(f2tf32(v.y - h));
            h = __uint_as_float(f2tf32(v.z)); dh[2] = h; dl[2] = __uint_as_float(f2tf32(v.z - h));
            h = __uint_as_float(f2tf32(v.w)); dh[3] = h; dl[3] = __uint_as_float(f2tf32(v.w - h));
        }
        __syncthreads();
#pragma unroll
        for (int ks = 0; ks < PKC / 8; ++ks) {
            uint32_t ah[4], al[4];
            ah[0] = __float_as_uint(Es[0][ar * ES_S + ks * 8 + ac]);
            ah[1] = __float_as_uint(Es[0][(ar + 8) * ES_S + ks * 8 + ac]);
            ah[2] = __float_as_uint(Es[0][ar * ES_S + ks * 8 + ac + 4]);
            ah[3] = __float_as_uint(Es[0][(ar + 8) * ES_S + ks * 8 + ac + 4]);
            al[0] = __float_as_uint(Es[1][ar * ES_S + ks * 8 + ac]);
            al[1] = __float_as_uint(Es[1][(ar + 8) * ES_S + ks * 8 + ac]);
            al[2] = __float_as_uint(Es[1][ar * ES_S + ks * 8 + ac + 4]);
            al[3] = __float_as_uint(Es[1][(ar + 8) * ES_S + ks * 8 + ac + 4]);
#pragma unroll
            for (int w = 0; w < 3; ++w) {
#pragma unroll
                for (int n = 0; n < 4; ++n) {
                    const int brow = ks * 8 + ac;
                    const int bcol = ch * 32 + n * 8 + g;
                    uint32_t bh[2], bl[2];
                    bh[0] = __float_as_uint(Ws[0][w][brow * WS_S + bcol]);
                    bh[1] = __float_as_uint(Ws[0][w][(brow + 4) * WS_S + bcol]);
                    bl[0] = __float_as_uint(Ws[1][w][brow * WS_S + bcol]);
                    bl[1] = __float_as_uint(Ws[1][w][(brow + 4) * WS_S + bcol]);
                    mma_tf32(acc[w][n], ah, bh);
                    mma_tf32(acc[w][n], ah, bl);
                    mma_tf32(acc[w][n], al, bh);
                }
            }
        }
    }
    const float* bias[3] = {bq, bk, bv};
    float* outp[3] = {g_Q, g_K, g_V};
    const int r  = row0 + ar;
    const int cb = ac * 2;
#pragma unroll
    for (int w = 0; w < 3; ++w) {
#pragma unroll
        for (int n = 0; n < 4; ++n) {
            int col = ch * 32 + n * 8 + cb;
            float b0 = bias[w][col], b1 = bias[w][col + 1];
            *reinterpret_cast<float2*>(&outp[w][(size_t)r * DK_C + col]) =
                make_float2(acc[w][n][0] + b0, acc[w][n][1] + b1);
            *reinterpret_cast<float2*>(&outp[w][(size_t)(r + 8) * DK_C + col]) =
                make_float2(acc[w][n][2] + b0, acc[w][n][3] + b1);
        }
    }
}

// ---------------------------------------------------------------------------
// Kernel 2: flash attention, split-KV (4 splits). Br=Bc=64, 4 warps.
// K/P buffer stride 68 (conflict-free row-indexed frag loads),
// V buffer stride 72 (conflict-free col-indexed frag loads).
// Writes unnormalized partial O + (m, l) per row per split.
// ---------------------------------------------------------------------------
#define KPS 68
#define VSS 72

__global__ __launch_bounds__(128)
void attn_kernel()
{
    __shared__ float KP[64 * KPS];   // Q staging, then K tile, then P tile
    __shared__ float Vs[64 * VSS];   // V tile

    const int tid   = threadIdx.x;
    const int warp  = tid >> 5;
    const int lane  = tid & 31;
    const int b     = blockIdx.y;
    const int q0    = blockIdx.x * 64;
    const int split = blockIdx.z;
    const int t0    = split * TILES_PER_SPLIT;

    const float* Qg = g_Q + ((size_t)b * S_C + q0) * DK_C;
    const float* Kg = g_K + (size_t)b * S_C * DK_C;
    const float* Vg = g_V + (size_t)b * S_C * DK_C;

    // Stage Q tile raw
#pragma unroll
    for (int i = 0; i < 8; ++i) {
        int id = tid + i * 128;
        int r = id >> 4, c4 = (id & 15) * 4;
        *reinterpret_cast<float4*>(&KP[r * KPS + c4]) =
            *reinterpret_cast<const float4*>(&Qg[(size_t)r * DK_C + c4]);
    }
    __syncthreads();

    const int ar = warp * 16 + (lane >> 2);
    const int ac = lane & 3;
    const int g  = lane >> 2;
    const float qsc = 1.4426950408889634f * 0.125f;  // log2(e)/sqrt(dk)
    uint32_t qf[8][4];
#pragma unroll
    for (int ks = 0; ks < 8; ++ks) {
        qf[ks][0] = f2tf32(KP[ar * KPS + ks * 8 + ac] * qsc);
        qf[ks][1] = f2tf32(KP[(ar + 8) * KPS + ks * 8 + ac] * qsc);
        qf[ks][2] = f2tf32(KP[ar * KPS + ks * 8 + ac + 4] * qsc);
        qf[ks][3] = f2tf32(KP[(ar + 8) * KPS + ks * 8 + ac + 4] * qsc);
    }

    float o[8][4];
#pragma unroll
    for (int n = 0; n < 8; ++n)
#pragma unroll
        for (int j = 0; j < 4; ++j) o[n][j] = 0.f;
    float m0 = -1e30f, m1 = -1e30f, l0 = 0.f, l1 = 0.f;

    for (int tt = 0; tt < TILES_PER_SPLIT; ++tt) {
        const int t = t0 + tt;
        __syncthreads();
        const float* Kt = Kg + (size_t)t * 64 * DK_C;
        const float* Vt = Vg + (size_t)t * 64 * DK_C;
#pragma unroll
        for (int i = 0; i < 8; ++i) {
            int id = tid + i * 128;
            int r = id >> 4, c4 = (id & 15) * 4;
            float4 kv = *reinterpret_cast<const float4*>(&Kt[(size_t)r * DK_C + c4]);
            float4 vv = *reinterpret_cast<const float4*>(&Vt[(size_t)r * DK_C + c4]);
            float* kd = &KP[r * KPS + c4];
            float* vd = &Vs[r * VSS + c4];
            kd[0] = __uint_as_float(f2tf32(kv.x));
            kd[1] = __uint_as_float(f2tf32(kv.y));
            kd[2] = __uint_as_float(f2tf32(kv.z));
            kd[3] = __uint_as_float(f2tf32(kv.w));
            vd[0] = __uint_as_float(f2tf32(vv.x));
            vd[1] = __uint_as_float(f2tf32(vv.y));
            vd[2] = __uint_as_float(f2tf32(vv.z));
            vd[3] = __uint_as_float(f2tf32(vv.w));
        }
        __syncthreads();

        // S = (Q * qsc) @ K^T
        float s[8][4];
#pragma unroll
        for (int n = 0; n < 8; ++n)
#pragma unroll
            for (int j = 0; j < 4; ++j) s[n][j] = 0.f;
#pragma unroll
        for (int ks = 0; ks < 8; ++ks) {
#pragma unroll
            for (int n = 0; n < 8; ++n) {
                uint32_t bf[2];
                bf[0] = __float_as_uint(KP[(n * 8 + g) * KPS + ks * 8 + ac]);
                bf[1] = __float_as_uint(KP[(n * 8 + g) * KPS + ks * 8 + ac + 4]);
                mma_tf32(s[n], qf[ks], bf);
            }
        }

        // Online softmax (log2 domain)
        float mx0 = m0, mx1 = m1;
#pragma unroll
        for (int n = 0; n < 8; ++n) {
            mx0 = fmaxf(mx0, fmaxf(s[n][0], s[n][1]));
            mx1 = fmaxf(mx1, fmaxf(s[n][2], s[n][3]));
        }
        mx0 = fmaxf(mx0, __shfl_xor_sync(0xffffffffu, mx0, 1));
        mx0 = fmaxf(mx0, __shfl_xor_sync(0xffffffffu, mx0, 2));
        mx1 = fmaxf(mx1, __shfl_xor_sync(0xffffffffu, mx1, 1));
        mx1 = fmaxf(mx1, __shfl_xor_sync(0xffffffffu, mx1, 2));
        float a0 = exp2_approx(m0 - mx0);
        float a1 = exp2_approx(m1 - mx1);
        float rs0 = 0.f, rs1 = 0.f;
#pragma unroll
        for (int n = 0; n < 8; ++n) {
            s[n][0] = exp2_approx(s[n][0] - mx0);
            s[n][1] = exp2_approx(s[n][1] - mx0);
            s[n][2] = exp2_approx(s[n][2] - mx1);
            s[n][3] = exp2_approx(s[n][3] - mx1);
            rs0 += s[n][0] + s[n][1];
            rs1 += s[n][2] + s[n][3];
        }
        rs0 += __shfl_xor_sync(0xffffffffu, rs0, 1);
        rs0 += __shfl_xor_sync(0xffffffffu, rs0, 2);
        rs1 += __shfl_xor_sync(0xffffffffu, rs1, 1);
        rs1 += __shfl_xor_sync(0xffffffffu, rs1, 2);
        l0 = l0 * a0 + rs0;
        l1 = l1 * a1 + rs1;
        m0 = mx0; m1 = mx1;
#pragma unroll
        for (int n = 0; n < 8; ++n) {
            o[n][0] *= a0; o[n][1] *= a0; o[n][2] *= a1; o[n][3] *= a1;
        }

        __syncthreads();   // all warps done reading K tile before P overwrite
        {
            const int pc = ac * 2;
#pragma unroll
            for (int n = 0; n < 8; ++n) {
                KP[ar * KPS + n * 8 + pc]           = __uint_as_float(f2tf32(s[n][0]));
                KP[ar * KPS + n * 8 + pc + 1]       = __uint_as_float(f2tf32(s[n][1]));
                KP[(ar + 8) * KPS + n * 8 + pc]     = __uint_as_float(f2tf32(s[n][2]));
                KP[(ar + 8) * KPS + n * 8 + pc + 1] = __uint_as_float(f2tf32(s[n][3]));
            }
        }
        __syncwarp();      // P rows are warp-private

        // O += P @ V
#pragma unroll
        for (int ks = 0; ks < 8; ++ks) {
            uint32_t a[4];
            a[0] = __float_as_uint(KP[ar * KPS + ks * 8 + ac]);
            a[1] = __float_as_uint(KP[(ar + 8) * KPS + ks * 8 + ac]);
            a[2] = __float_as_uint(KP[ar * KPS + ks * 8 + ac + 4]);
            a[3] = __float_as_uint(KP[(ar + 8) * KPS + ks * 8 + ac + 4]);
#pragma unroll
            for (int n = 0; n < 8; ++n) {
                uint32_t bf[2];
                bf[0] = __float_as_uint(Vs[(ks * 8 + ac) * VSS + n * 8 + g]);
                bf[1] = __float_as_uint(Vs[(ks * 8 + ac + 4) * VSS + n * 8 + g]);
                mma_tf32(o[n], a, bf);
            }
        }
    }

    // Epilogue: store unnormalized partial O and (m, l)
    float* op = g_Opart + ((size_t)split * NROWS_C + (size_t)b * S_C + q0) * DK_C;
    const int cb = ac * 2;
#pragma unroll
    for (int n = 0; n < 8; ++n) {
        int col = n * 8 + cb;
        *reinterpret_cast<float2*>(&op[(size_t)ar * DK_C + col]) =
            make_float2(o[n][0], o[n][1]);
        *reinterpret_cast<float2*>(&op[(size_t)(ar + 8) * DK_C + col]) =
            make_float2(o[n][2], o[n][3]);
    }
    if (ac == 0) {
        size_t base = (size_t)split * NROWS_C + (size_t)b * S_C + q0;
        g_m[base + ar] = m0;     g_l[base + ar] = l0;
        g_m[base + ar + 8] = m1; g_l[base + ar + 8] = l1;
    }
}

// ---------------------------------------------------------------------------
// Kernel 3: combine partial results across splits.
// ---------------------------------------------------------------------------
__global__ __launch_bounds__(256)
void combine_kernel(float* __restrict__ out)
{
    int idx = blockIdx.x * 256 + threadIdx.x;   // NROWS_C * 16 total
    int row = idx >> 4;
    int c4  = (idx & 15) * 4;

    float ms[NSPLIT];
    float m = -1e30f;
#pragma unroll
    for (int s = 0; s < NSPLIT; ++s) {
        ms[s] = g_m[(size_t)s * NROWS_C + row];
        m = fmaxf(m, ms[s]);
    }
    float l = 0.f;
    float ox = 0.f, oy = 0.f, oz = 0.f, ow = 0.f;
#pragma unroll
    for (int s = 0; s < NSPLIT; ++s) {
        float w = exp2_approx(ms[s] - m);
        l += g_l[(size_t)s * NROWS_C + row] * w;
        float4 p = *reinterpret_cast<const float4*>(
            &g_Opart[((size_t)s * NROWS_C + row) * DK_C + c4]);
        ox += p.x * w; oy += p.y * w; oz += p.z * w; ow += p.w * w;
    }
    float inv = 1.f / l;
    *reinterpret_cast<float4*>(&out[(size_t)row * DK_C + c4]) =
        make_float4(ox * inv, oy * inv, oz * inv, ow * inv);
}

// ---------------------------------------------------------------------------
extern "C" void kernel_launch(void* const* d_in, const int* in_sizes, int n_in,
                              void* d_out, int out_size) {
    (void)in_sizes; (void)n_in; (void)out_size;
    const float* emb = (const float*)d_in[0];
    const float* Wq  = (const float*)d_in[1];
    const float* bq  = (const float*)d_in[2];
    const float* Wk  = (const float*)d_in[3];
    const float* bk  = (const float*)d_in[4];
    const float* Wv  = (const float*)d_in[5];
    const float* bv  = (const float*)d_in[6];

    qkv_proj_kernel<<<NROWS_C / 64, 256>>>(emb, Wq, bq, Wk, bk, Wv, bv);
    dim3 agrid(S_C / 64, B_C, NSPLIT);
    attn_kernel<<<agrid, 128>>>();
    combine_kernel<<<(NROWS_C * 16) / 256, 256>>>((float*)d_out);
}